// round 8
// baseline (speedup 1.0000x reference)
#include <cuda_runtime.h>
#include <cuda_fp16.h>

// VQ-VAE forward — fp8(e4m3) legacy-mma candidate filter + exact fp32 rescore.
// Exact numerics (XLA-CPU sequential chains) preserved for all outputs.
// NOTE: bench toolchain targets compute_103 (no 'a') => no tcgen05; fp8
// mma.sync (sm_89+ base feature) halves MMA instruction count vs fp16.

#define N_PIX 32768
#define D_DIM 256
#define K_CB  4096
#define CAP   64
#define MARGIN 1.0e-3f
#define KSCALE 4.8828125e-4f   // 2/4096 (descale of fp8 acc)

// ---- scratch (static device globals; no allocation) ----
__device__ float g_z[N_PIX * D_DIM];          // 32 MB pre-VQ activations [n][d]
__device__ unsigned char g_z8[N_PIX * D_DIM]; // 8 MB e4m3 copy (filter only)
__device__ unsigned g_e8[K_CB * 64];          // 1 MB e4m3 emb*4096, 4 dims/u32
__device__ float g_wt[D_DIM * D_DIM];
__device__ float g_esq[K_CB];
__device__ float g_zsq[N_PIX];
__device__ int   g_idx[N_PIX];
__device__ unsigned int g_counts[K_CB];
__device__ float g_loss;
__device__ unsigned short g_cand[N_PIX * CAP];
__device__ int g_ccnt[N_PIX];

__device__ __forceinline__ void cp16(void* dst, const void* src) {
    unsigned d = (unsigned)__cvta_generic_to_shared(dst);
    asm volatile("cp.async.cg.shared.global [%0], [%1], 16;\n" :: "r"(d), "l"(src));
}
// pack two floats -> e4m3x2 (lo byte = b operand, hi byte = a operand)
__device__ __forceinline__ unsigned short f2_e4m3x2(float hi, float lo) {
    unsigned short u;
    asm("cvt.rn.satfinite.e4m3x2.f32 %0, %1, %2;" : "=h"(u) : "f"(hi), "f"(lo));
    return u;
}

// ============================================================
// prep: transpose W, zero counts/loss
// ============================================================
__global__ void prep_kernel(const float* __restrict__ conv_w) {
    int gid = blockIdx.x * 256 + threadIdx.x;
    if (gid < D_DIM * D_DIM) {
        int c = gid >> 8, d = gid & 255;
        g_wt[gid] = conv_w[d * D_DIM + c];
    }
    if (gid < K_CB) g_counts[gid] = 0u;
    if (gid == 0) g_loss = 0.f;
}

// ============================================================
// esq: strict sequential ascending-d chain; also emit e4m3
// codebook * 4096 (exact pow2) packed 4 dims per u32.
// ============================================================
__global__ void esq_kernel(const float* __restrict__ emb) {
    int k = blockIdx.x * 256 + threadIdx.x;
    if (k >= K_CB) return;
    const float4* er = (const float4*)(emb + (size_t)k * D_DIM);
    float s = 0.f;
    #pragma unroll 8
    for (int i = 0; i < 64; i++) {
        float4 v = er[i];
        s = __fadd_rn(s, __fmul_rn(v.x, v.x));
        s = __fadd_rn(s, __fmul_rn(v.y, v.y));
        s = __fadd_rn(s, __fmul_rn(v.z, v.z));
        s = __fadd_rn(s, __fmul_rn(v.w, v.w));
        unsigned short u0 = f2_e4m3x2(v.y * 4096.f, v.x * 4096.f);
        unsigned short u1 = f2_e4m3x2(v.w * 4096.f, v.z * 4096.f);
        g_e8[k * 64 + i] = ((unsigned)u1 << 16) | u0;
    }
    g_esq[k] = s;
}

// ============================================================
// conv: Eigen-order ascending-c FMA chain, bias last; + e4m3 copy
// ============================================================
__global__ __launch_bounds__(256) void conv_kernel(const float* __restrict__ x,
                                                   const float* __restrict__ conv_b) {
    __shared__ float xs[D_DIM * 32];
    int t = threadIdx.x;
    int n0 = blockIdx.x * 32;
    int b = n0 >> 10, h = (n0 >> 5) & 31;
    const float* xb = x + (size_t)b * (D_DIM * 1024) + h * 32;

    int lane = t & 31, cg = t >> 5;
    #pragma unroll 4
    for (int i = 0; i < 32; i++) {
        int c = cg * 32 + i;
        xs[c * 32 + lane] = xb[c * 1024 + lane];
    }
    __syncthreads();

    int d = t;
    float4 acc[8];
    #pragma unroll
    for (int p = 0; p < 8; p++) acc[p] = make_float4(0.f, 0.f, 0.f, 0.f);
    const float4* xs4 = (const float4*)xs;

    for (int c0 = 0; c0 < D_DIM; c0 += 8) {
        float w[8];
        #pragma unroll
        for (int cc = 0; cc < 8; cc++) w[cc] = g_wt[(c0 + cc) * D_DIM + d];
        #pragma unroll
        for (int p4 = 0; p4 < 8; p4++) {
            #pragma unroll
            for (int cc = 0; cc < 8; cc++) {
                float4 xv = xs4[(c0 + cc) * 8 + p4];
                acc[p4].x = __fmaf_rn(xv.x, w[cc], acc[p4].x);
                acc[p4].y = __fmaf_rn(xv.y, w[cc], acc[p4].y);
                acc[p4].z = __fmaf_rn(xv.z, w[cc], acc[p4].z);
                acc[p4].w = __fmaf_rn(xv.w, w[cc], acc[p4].w);
            }
        }
    }
    float cb = conv_b[d];
    #pragma unroll
    for (int p4 = 0; p4 < 8; p4++) {
        float v0 = __fadd_rn(acc[p4].x, cb);
        float v1 = __fadd_rn(acc[p4].y, cb);
        float v2 = __fadd_rn(acc[p4].z, cb);
        float v3 = __fadd_rn(acc[p4].w, cb);
        g_z[(size_t)(n0 + p4 * 4 + 0) * D_DIM + d] = v0;
        g_z[(size_t)(n0 + p4 * 4 + 1) * D_DIM + d] = v1;
        g_z[(size_t)(n0 + p4 * 4 + 2) * D_DIM + d] = v2;
        g_z[(size_t)(n0 + p4 * 4 + 3) * D_DIM + d] = v3;
        g_z8[(size_t)(n0 + p4 * 4 + 0) * D_DIM + d] = (unsigned char)f2_e4m3x2(0.f, v0);
        g_z8[(size_t)(n0 + p4 * 4 + 1) * D_DIM + d] = (unsigned char)f2_e4m3x2(0.f, v1);
        g_z8[(size_t)(n0 + p4 * 4 + 2) * D_DIM + d] = (unsigned char)f2_e4m3x2(0.f, v2);
        g_z8[(size_t)(n0 + p4 * 4 + 3) * D_DIM + d] = (unsigned char)f2_e4m3x2(0.f, v3);
    }
}

// ============================================================
// zsq: strict sequential ascending-d chain
// ============================================================
__global__ void zsq_kernel() {
    int n = blockIdx.x * 256 + threadIdx.x;
    const float4* zr = (const float4*)(g_z + (size_t)n * D_DIM);
    float s = 0.f;
    #pragma unroll 16
    for (int i = 0; i < 64; i++) {
        float4 v = zr[i];
        s = __fadd_rn(s, __fmul_rn(v.x, v.x));
        s = __fadd_rn(s, __fmul_rn(v.y, v.y));
        s = __fadd_rn(s, __fmul_rn(v.z, v.z));
        s = __fadd_rn(s, __fmul_rn(v.w, v.w));
    }
    g_zsq[n] = s;
}

// ============================================================
// dist_mma: e4m3 m16n8k32 mma filter; per-pixel shared running
// min + candidate push within MARGIN. CTA = 128 pixels, 32
// code-tiles of 128, E staged 64-dim chunks (2-stage cp.async).
// smem: zA 32KB (A-frag u32, 4 dims each) | eB 2x10KB (stride
// 80B/code row, conflict-free) | misc 2KB | cand 16KB = 70KB.
// ============================================================
#define EBS_U32 20   // 80 bytes per code row (64 used)
__global__ void __launch_bounds__(256, 2) dist_mma_kernel() {
    extern __shared__ char smem[];
    unsigned* zA   = (unsigned*)smem;                       // 32768 B (8192 u32)
    unsigned* eB   = (unsigned*)(smem + 32768);             // 20480 B
    float* zsq_s = (float*)(smem + 32768 + 20480);          // 512 B
    float* esq_s = zsq_s + 128;
    float* minv  = esq_s + 128;
    int*   cnt_s = (int*)(minv + 128);
    unsigned short* cand_s = (unsigned short*)(cnt_s + 128); // 16384 B

    int t = threadIdx.x;
    int lane = t & 31, warp = t >> 5;
    int wm = warp >> 2, wn = warp & 3;         // 2 x 4 warp grid
    int g = lane >> 2, q = lane & 3;
    int n0 = blockIdx.x * 128;

    if (t < 128) { zsq_s[t] = g_zsq[n0 + t]; minv[t] = 3.0e38f; cnt_s[t] = 0; }

    // stage Z tile: coalesced u32 reads of g_z8 (4 dims each), scatter into
    // m16n8k32 A-frag order: zA[(ks32*8+mtile)*128 + (g*4+q)*4 + hi + 2*khi]
    const unsigned* z832 = (const unsigned*)g_z8;
    #pragma unroll 4
    for (int l = 0; l < 32; l++) {
        int idx = t + 256 * l;                 // 8192 u32
        int srow = idx >> 6, c4 = idx & 63;
        unsigned v = z832[(size_t)(n0 + srow) * 64 + c4];
        int mtile = srow >> 4, rr = srow & 15, gg = rr & 7, hi = rr >> 3;
        int ks = c4 >> 3, rem = c4 & 7, khi = rem >> 2, qq = rem & 3;
        zA[(ks * 8 + mtile) * 128 + (gg * 4 + qq) * 4 + (hi + 2 * khi)] = v;
    }

    // prologue: stage 0 (kt=0, kc=0): 128 code rows x 64 bytes
    {
        const char* src0 = (const char*)g_e8;
        #pragma unroll
        for (int l = 0; l < 2; l++) {
            int idx = t + 256 * l;             // 512 cp16
            int crow = idx >> 2, seg = idx & 3;
            cp16((char*)eB + crow * 80 + seg * 16,
                 src0 + (size_t)crow * 256 + seg * 16);
        }
        asm volatile("cp.async.commit_group;\n");
    }

    float acc[4][4][4];
    float lbest[8];
    #pragma unroll
    for (int i = 0; i < 8; i++) lbest[i] = 3.0e38f;

    #pragma unroll 1
    for (int s = 0; s < 128; s++) {
        int kc = s & 3, buf = s & 1, kt = s >> 2;
        if (s + 1 < 128) {
            int kt1 = (s + 1) >> 2, kc1 = (s + 1) & 3, buf1 = (s + 1) & 1;
            char* dbase = (char*)eB + buf1 * 10240;
            const char* src0 = (const char*)g_e8 + (size_t)(kt1 * 128) * 256 + kc1 * 64;
            #pragma unroll
            for (int l = 0; l < 2; l++) {
                int idx = t + 256 * l;
                int crow = idx >> 2, seg = idx & 3;
                cp16(dbase + crow * 80 + seg * 16,
                     src0 + (size_t)crow * 256 + seg * 16);
            }
            asm volatile("cp.async.commit_group;\n");
            asm volatile("cp.async.wait_group 1;\n");
        } else {
            asm volatile("cp.async.wait_group 0;\n");
        }
        __syncthreads();

        if (kc == 0) {
            if (t < 128) esq_s[t] = g_esq[kt * 128 + t];
            #pragma unroll
            for (int mi = 0; mi < 4; mi++)
                #pragma unroll
                for (int ni = 0; ni < 4; ni++)
                    #pragma unroll
                    for (int c = 0; c < 4; c++) acc[mi][ni][c] = 0.f;
        }

        unsigned* ebuf = eB + buf * (10240 / 4);
        #pragma unroll
        for (int ks = 0; ks < 2; ks++) {       // 2 k-steps of 32 dims
            int kg = kc * 2 + ks;              // absolute kstep32 (0..7)
            unsigned a[4][4], bfr[4][2];
            #pragma unroll
            for (int mi = 0; mi < 4; mi++) {
                int mtile = wm * 4 + mi;
                uint4 av = ((const uint4*)zA)[(kg * 8 + mtile) * 32 + lane];
                a[mi][0] = av.x; a[mi][1] = av.y; a[mi][2] = av.z; a[mi][3] = av.w;
            }
            #pragma unroll
            for (int ni = 0; ni < 4; ni++) {
                int cl = wn * 32 + ni * 8 + g;
                bfr[ni][0] = ebuf[cl * EBS_U32 + ks * 8 + q];
                bfr[ni][1] = ebuf[cl * EBS_U32 + ks * 8 + 4 + q];
            }
            #pragma unroll
            for (int mi = 0; mi < 4; mi++)
                #pragma unroll
                for (int ni = 0; ni < 4; ni++)
                    asm volatile(
                        "mma.sync.aligned.m16n8k32.row.col.f32.e4m3.e4m3.f32 "
                        "{%0,%1,%2,%3}, {%4,%5,%6,%7}, {%8,%9}, {%0,%1,%2,%3};"
                        : "+f"(acc[mi][ni][0]), "+f"(acc[mi][ni][1]),
                          "+f"(acc[mi][ni][2]), "+f"(acc[mi][ni][3])
                        : "r"(a[mi][0]), "r"(a[mi][1]), "r"(a[mi][2]), "r"(a[mi][3]),
                          "r"(bfr[ni][0]), "r"(bfr[ni][1]));
        }

        if (kc == 3) {
            #pragma unroll
            for (int mi = 0; mi < 4; mi++) {
                #pragma unroll
                for (int hi = 0; hi < 2; hi++) {
                    int r = wm * 64 + mi * 16 + hi * 8 + g;
                    float zq = zsq_s[r];
                    int slot = mi * 2 + hi;
                    #pragma unroll
                    for (int ni = 0; ni < 4; ni++) {
                        #pragma unroll
                        for (int cc = 0; cc < 2; cc++) {
                            int col = wn * 32 + ni * 8 + 2 * q + cc;
                            float gv = acc[mi][ni][hi * 2 + cc];
                            // descale: acc = 4096 * z.e  =>  -2g = -acc/2048
                            float sv = __fadd_rn(zq, esq_s[col]) - gv * KSCALE;
                            if (sv < lbest[slot] + MARGIN) {
                                atomicMin((int*)&minv[r], __float_as_int(sv)); // dist>0
                                float cm = minv[r];
                                if (sv < cm + MARGIN) {
                                    int pos = atomicAdd(&cnt_s[r], 1);
                                    if (pos < CAP)
                                        cand_s[r * CAP + pos] = (unsigned short)(kt * 128 + col);
                                }
                                if (sv < lbest[slot]) lbest[slot] = sv;
                            }
                        }
                    }
                }
            }
        }
        __syncthreads();
    }

    if (t < 128) g_ccnt[n0 + t] = cnt_s[t];
    for (int i = t; i < 128 * CAP; i += 256)
        g_cand[(size_t)n0 * CAP + i] = cand_s[i];
}

// ============================================================
// rescore: EXACT ascending-d FMA chain for candidates only;
// packed-u64 min => lowest-index tie-break. Warp per pixel.
// Overflowed pixels: full exact scan (rare).
// ============================================================
__global__ void __launch_bounds__(256) rescore_kernel(const float* __restrict__ emb) {
    __shared__ float zrow[8][256];
    int t = threadIdx.x, lane = t & 31, w = t >> 5;
    int n = blockIdx.x * 8 + w;

    #pragma unroll
    for (int l = 0; l < 2; l++) {
        int f4 = lane + 32 * l;
        ((float4*)zrow[w])[f4] = ((const float4*)g_z)[(size_t)n * 64 + f4];
    }
    __syncwarp();

    int cnt = g_ccnt[n];
    float zq = g_zsq[n];
    const float4* z4 = (const float4*)zrow[w];
    unsigned long long best = 0xFFFFFFFFFFFFFFFFull;

    int total = (cnt <= CAP) ? cnt : K_CB;
    for (int i = lane; i < total; i += 32) {
        int k = (cnt <= CAP) ? (int)g_cand[(size_t)n * CAP + i] : i;
        float a = 0.f;
        const float4* e4 = (const float4*)(emb + (size_t)k * D_DIM);
        #pragma unroll 8
        for (int d4 = 0; d4 < 64; d4++) {
            float4 ev = e4[d4], zv = z4[d4];
            a = __fmaf_rn(zv.x, ev.x, a);
            a = __fmaf_rn(zv.y, ev.y, a);
            a = __fmaf_rn(zv.z, ev.z, a);
            a = __fmaf_rn(zv.w, ev.w, a);
        }
        float s = __fadd_rn(__fadd_rn(zq, g_esq[k]), -2.f * a);
        unsigned u = __float_as_uint(s);
        u = (u & 0x80000000u) ? ~u : (u | 0x80000000u);
        unsigned long long key = ((unsigned long long)u << 32) | (unsigned)k;
        if (key < best) best = key;
    }
    #pragma unroll
    for (int off = 16; off; off >>= 1) {
        unsigned long long o = __shfl_xor_sync(0xffffffffu, best, off);
        if (o < best) best = o;
    }
    if (lane == 0) g_idx[n] = (int)(best & 0xFFFFFFFFu);
}

// ============================================================
// epilogue: out = fl(z + fl(q - z)); loss partials; histogram
// ============================================================
__global__ __launch_bounds__(256) void epilogue_kernel(const float* __restrict__ emb,
                                                       float* __restrict__ out) {
    __shared__ float st_s[D_DIM * 33];
    __shared__ int idx_s[32];
    __shared__ float wsum[8];
    int t = threadIdx.x;
    int bh = blockIdx.x;
    int b = bh >> 5, h = bh & 31;
    int n0 = bh * 32;

    if (t < 32) idx_s[t] = g_idx[n0 + t];
    __syncthreads();

    float lsum = 0.f;
    for (int p = 0; p < 32; p++) {
        float zv = g_z[(size_t)(n0 + p) * D_DIM + t];
        float qv = emb[(size_t)idx_s[p] * D_DIM + t];
        float diff = __fadd_rn(qv, -zv);
        lsum += diff * diff;
        st_s[t * 33 + p] = __fadd_rn(zv, diff);
    }
    __syncthreads();

    int w = t & 31, dg = t >> 5;
    float* ob = out + (size_t)b * (D_DIM * 1024) + h * 32;
    #pragma unroll 4
    for (int dd = 0; dd < 32; dd++) {
        int d = dg * 32 + dd;
        ob[(size_t)d * 1024 + w] = st_s[d * 33 + w];
    }

    #pragma unroll
    for (int off = 16; off; off >>= 1) lsum += __shfl_xor_sync(0xffffffffu, lsum, off);
    if ((t & 31) == 0) wsum[t >> 5] = lsum;
    __syncthreads();
    if (t == 0) {
        float s = 0.f;
        #pragma unroll
        for (int i = 0; i < 8; i++) s += wsum[i];
        atomicAdd(&g_loss, s);
    }
    if (t < 32) atomicAdd(&g_counts[idx_s[t]], 1u);
}

// ============================================================
// finalize
// ============================================================
__global__ void finalize_kernel(float* __restrict__ out, int out_size) {
    __shared__ float red[512];
    int t = threadIdx.x;
    float s = 0.f;
    for (int k = t; k < K_CB; k += 512) {
        float avg = (float)g_counts[k] / (float)N_PIX;
        s += avg * logf(avg + 1e-10f);
    }
    red[t] = s;
    __syncthreads();
    for (int o = 256; o; o >>= 1) {
        if (t < o) red[t] += red[t + o];
        __syncthreads();
    }
    if (t == 0) {
        out[out_size - 2] = 1.25f * (g_loss / (float)(N_PIX * D_DIM));
        out[out_size - 1] = expf(-red[0]);
    }
}

extern "C" void kernel_launch(void* const* d_in, const int* in_sizes, int n_in,
                              void* d_out, int out_size) {
    const float* x      = (const float*)d_in[0];
    const float* conv_w = (const float*)d_in[1];
    const float* conv_b = (const float*)d_in[2];
    const float* emb    = (const float*)d_in[3];
    float* out = (float*)d_out;

    const int DIST_SMEM = 32768 + 20480 + 4 * 512 + 16384;   // 71680 B
    cudaFuncSetAttribute(dist_mma_kernel,
                         cudaFuncAttributeMaxDynamicSharedMemorySize, DIST_SMEM);

    prep_kernel<<<257, 256>>>(conv_w);
    esq_kernel<<<16, 256>>>(emb);
    conv_kernel<<<N_PIX / 32, 256>>>(x, conv_b);
    zsq_kernel<<<N_PIX / 256, 256>>>();
    dist_mma_kernel<<<N_PIX / 128, 256, DIST_SMEM>>>();
    rescore_kernel<<<N_PIX / 8, 256>>>(emb);
    epilogue_kernel<<<N_PIX / 32, 256>>>(emb, out);
    finalize_kernel<<<1, 512>>>(out, out_size);
}

// round 9
// speedup vs baseline: 6.9509x; 6.9509x over previous
#include <cuda_runtime.h>
#include <cuda_fp16.h>

// VQ-VAE forward — fp16 mma filter (barrier-free streaming) + exact fp32 rescore.
// Exact numerics (XLA-CPU sequential chains) preserved for all outputs.

#define N_PIX 32768
#define D_DIM 256
#define K_CB  4096
#define CAP   64
#define MARGIN 2.5e-4f
#define KSCALE 4.8828125e-4f   // 2/4096 (descale of x4096-scaled fp16 acc)

// ---- scratch (static device globals; no allocation) ----
__device__ float g_z[N_PIX * D_DIM];          // 32 MB pre-VQ activations [n][d]
__device__ __half g_zh[N_PIX * D_DIM];        // 16 MB fp16 copy (filter only)
__device__ uint2 g_ebp[K_CB * 64];            // 2 MB emb*4096 fp16, B-frag-major
__device__ float g_wt[D_DIM * D_DIM];
__device__ float g_esq[K_CB];
__device__ float g_zsq[N_PIX];
__device__ int   g_idx[N_PIX];
__device__ unsigned int g_counts[K_CB];
__device__ float g_loss;
__device__ unsigned short g_cand[N_PIX * CAP];
__device__ int g_ccnt[N_PIX];

// ============================================================
// prep: transpose W, zero counts/loss
// ============================================================
__global__ void prep_kernel(const float* __restrict__ conv_w) {
    int gid = blockIdx.x * 256 + threadIdx.x;
    if (gid < D_DIM * D_DIM) {
        int c = gid >> 8, d = gid & 255;
        g_wt[gid] = conv_w[d * D_DIM + c];
    }
    if (gid < K_CB) g_counts[gid] = 0u;
    if (gid == 0) g_loss = 0.f;
}

// ============================================================
// esq: strict sequential ascending-d chain; also pack fp16
// codebook * 4096 (exact pow2) into B-fragment-major layout:
// g_ebp[((kt*16+ks)*16 + wn*4+ni)*32 + g*4+q] = {b0,b1}
//   b0 = half2(e[16ks+2q], e[16ks+2q+1])
//   b1 = half2(e[16ks+2q+8], e[16ks+2q+9])
// where kt=k>>7, cl=k&127, wn=cl>>5, ni=(cl&31)>>3, g=cl&7.
// ============================================================
__global__ void esq_kernel(const float* __restrict__ emb) {
    int k = blockIdx.x * 256 + threadIdx.x;
    if (k >= K_CB) return;
    const float* ef = emb + (size_t)k * D_DIM;
    const float4* er = (const float4*)ef;
    float s = 0.f;
    #pragma unroll 8
    for (int i = 0; i < 64; i++) {
        float4 v = er[i];
        s = __fadd_rn(s, __fmul_rn(v.x, v.x));
        s = __fadd_rn(s, __fmul_rn(v.y, v.y));
        s = __fadd_rn(s, __fmul_rn(v.z, v.z));
        s = __fadd_rn(s, __fmul_rn(v.w, v.w));
    }
    g_esq[k] = s;

    int kt = k >> 7, cl = k & 127;
    int wn = cl >> 5, ni = (cl & 31) >> 3, gl = cl & 7;
    #pragma unroll 4
    for (int ks = 0; ks < 16; ks++) {
        #pragma unroll
        for (int q = 0; q < 4; q++) {
            int d0 = 16 * ks + 2 * q;
            __half2 b0 = __floats2half2_rn(ef[d0] * 4096.f,     ef[d0 + 1] * 4096.f);
            __half2 b1 = __floats2half2_rn(ef[d0 + 8] * 4096.f, ef[d0 + 9] * 4096.f);
            uint2 v;
            v.x = *(unsigned*)&b0;
            v.y = *(unsigned*)&b1;
            g_ebp[(size_t)(((kt * 16 + ks) * 16) + wn * 4 + ni) * 32 + gl * 4 + q] = v;
        }
    }
}

// ============================================================
// conv: Eigen-order ascending-c FMA chain, bias last; + fp16 copy
// ============================================================
__global__ __launch_bounds__(256) void conv_kernel(const float* __restrict__ x,
                                                   const float* __restrict__ conv_b) {
    __shared__ float xs[D_DIM * 32];
    int t = threadIdx.x;
    int n0 = blockIdx.x * 32;
    int b = n0 >> 10, h = (n0 >> 5) & 31;
    const float* xb = x + (size_t)b * (D_DIM * 1024) + h * 32;

    int lane = t & 31, cg = t >> 5;
    #pragma unroll 4
    for (int i = 0; i < 32; i++) {
        int c = cg * 32 + i;
        xs[c * 32 + lane] = xb[c * 1024 + lane];
    }
    __syncthreads();

    int d = t;
    float4 acc[8];
    #pragma unroll
    for (int p = 0; p < 8; p++) acc[p] = make_float4(0.f, 0.f, 0.f, 0.f);
    const float4* xs4 = (const float4*)xs;

    for (int c0 = 0; c0 < D_DIM; c0 += 8) {
        float w[8];
        #pragma unroll
        for (int cc = 0; cc < 8; cc++) w[cc] = g_wt[(c0 + cc) * D_DIM + d];
        #pragma unroll
        for (int p4 = 0; p4 < 8; p4++) {
            #pragma unroll
            for (int cc = 0; cc < 8; cc++) {
                float4 xv = xs4[(c0 + cc) * 8 + p4];
                acc[p4].x = __fmaf_rn(xv.x, w[cc], acc[p4].x);
                acc[p4].y = __fmaf_rn(xv.y, w[cc], acc[p4].y);
                acc[p4].z = __fmaf_rn(xv.z, w[cc], acc[p4].z);
                acc[p4].w = __fmaf_rn(xv.w, w[cc], acc[p4].w);
            }
        }
    }
    float cb = conv_b[d];
    #pragma unroll
    for (int p4 = 0; p4 < 8; p4++) {
        float v0 = __fadd_rn(acc[p4].x, cb);
        float v1 = __fadd_rn(acc[p4].y, cb);
        float v2 = __fadd_rn(acc[p4].z, cb);
        float v3 = __fadd_rn(acc[p4].w, cb);
        g_z[(size_t)(n0 + p4 * 4 + 0) * D_DIM + d] = v0;
        g_z[(size_t)(n0 + p4 * 4 + 1) * D_DIM + d] = v1;
        g_z[(size_t)(n0 + p4 * 4 + 2) * D_DIM + d] = v2;
        g_z[(size_t)(n0 + p4 * 4 + 3) * D_DIM + d] = v3;
        g_zh[(size_t)(n0 + p4 * 4 + 0) * D_DIM + d] = __float2half_rn(v0);
        g_zh[(size_t)(n0 + p4 * 4 + 1) * D_DIM + d] = __float2half_rn(v1);
        g_zh[(size_t)(n0 + p4 * 4 + 2) * D_DIM + d] = __float2half_rn(v2);
        g_zh[(size_t)(n0 + p4 * 4 + 3) * D_DIM + d] = __float2half_rn(v3);
    }
}

// ============================================================
// zsq: strict sequential ascending-d chain
// ============================================================
__global__ void zsq_kernel() {
    int n = blockIdx.x * 256 + threadIdx.x;
    const float4* zr = (const float4*)(g_z + (size_t)n * D_DIM);
    float s = 0.f;
    #pragma unroll 16
    for (int i = 0; i < 64; i++) {
        float4 v = zr[i];
        s = __fadd_rn(s, __fmul_rn(v.x, v.x));
        s = __fadd_rn(s, __fmul_rn(v.y, v.y));
        s = __fadd_rn(s, __fmul_rn(v.z, v.z));
        s = __fadd_rn(s, __fmul_rn(v.w, v.w));
    }
    g_zsq[n] = s;
}

// ============================================================
// dist_mma: fp16 m16n8k16 filter, barrier-free main loop.
// CTA = 128 pixels x 4096 codes (32 kt tiles of 128 codes).
// Z tile resident in smem (A-frag layout, staged once).
// B fragments streamed per-warp via coalesced LDG from g_ebp
// (L2-resident). esq via LDG. Scoring: per-pixel shared running
// min + candidate push within MARGIN (validated R5 logic).
// smem: zA 64KB | zsq/minv/cnt 1.5KB | cand 16KB = 81.5KB -> occ 2.
// ============================================================
__global__ void __launch_bounds__(256, 2) dist_mma_kernel() {
    extern __shared__ char smem[];
    unsigned* zA   = (unsigned*)smem;                        // 65536 B
    float* zsq_s = (float*)(smem + 65536);                   // 512 B
    float* minv  = zsq_s + 128;                              // 512 B
    int*   cnt_s = (int*)(minv + 128);                       // 512 B
    unsigned short* cand_s = (unsigned short*)(cnt_s + 128); // 16384 B

    int t = threadIdx.x;
    int lane = t & 31, warp = t >> 5;
    int wm = warp >> 2, wn = warp & 3;         // 2 x 4 warp grid
    int g = lane >> 2, q = lane & 3;
    int n0 = blockIdx.x * 128;

    if (t < 128) { zsq_s[t] = g_zsq[n0 + t]; minv[t] = 3.0e38f; cnt_s[t] = 0; }

    // stage Z tile: coalesced half2 reads, scatter into m16n8k16 A-frag order
    const unsigned* zh32 = (const unsigned*)g_zh;
    #pragma unroll 8
    for (int l = 0; l < 64; l++) {
        int idx = t + 256 * l;                 // 16384 u32
        int srow = idx >> 7, scol = idx & 127;
        unsigned v = zh32[(size_t)(n0 + srow) * 128 + scol];
        int mtile = srow >> 4, rr = srow & 15, gg = rr & 7, hi = rr >> 3;
        int ks = scol >> 3, rem = scol & 7, khi = rem >> 2, qq = rem & 3;
        zA[(ks * 8 + mtile) * 128 + (gg * 4 + qq) * 4 + (hi + 2 * khi)] = v;
    }
    __syncthreads();

    float lbest[8];
    #pragma unroll
    for (int i = 0; i < 8; i++) lbest[i] = 3.0e38f;

    const uint2* __restrict__ ebp = g_ebp;

    #pragma unroll 1
    for (int kt = 0; kt < 32; kt++) {
        // prefetch esq for this thread's 8 columns (latency hidden by MMAs)
        float eqv[4][2];
        #pragma unroll
        for (int ni = 0; ni < 4; ni++) {
            int cb = kt * 128 + wn * 32 + ni * 8 + 2 * q;
            eqv[ni][0] = g_esq[cb];
            eqv[ni][1] = g_esq[cb + 1];
        }

        float acc[4][4][4];
        #pragma unroll
        for (int mi = 0; mi < 4; mi++)
            #pragma unroll
            for (int ni = 0; ni < 4; ni++)
                #pragma unroll
                for (int c = 0; c < 4; c++) acc[mi][ni][c] = 0.f;

        #pragma unroll 4
        for (int ks = 0; ks < 16; ks++) {
            uint2 bv[4];
            #pragma unroll
            for (int ni = 0; ni < 4; ni++)
                bv[ni] = ebp[(size_t)((kt * 16 + ks) * 16 + wn * 4 + ni) * 32 + lane];
            #pragma unroll
            for (int mi = 0; mi < 4; mi++) {
                int mtile = wm * 4 + mi;
                uint4 av = ((const uint4*)zA)[(ks * 8 + mtile) * 32 + lane];
                #pragma unroll
                for (int ni = 0; ni < 4; ni++)
                    asm volatile(
                        "mma.sync.aligned.m16n8k16.row.col.f32.f16.f16.f32 "
                        "{%0,%1,%2,%3}, {%4,%5,%6,%7}, {%8,%9}, {%0,%1,%2,%3};"
                        : "+f"(acc[mi][ni][0]), "+f"(acc[mi][ni][1]),
                          "+f"(acc[mi][ni][2]), "+f"(acc[mi][ni][3])
                        : "r"(av.x), "r"(av.y), "r"(av.z), "r"(av.w),
                          "r"(bv[ni].x), "r"(bv[ni].y));
            }
        }

        // scoring: sv = fl(zsq+esq) - acc*(2/4096); margin filter (R5 logic)
        #pragma unroll
        for (int mi = 0; mi < 4; mi++) {
            #pragma unroll
            for (int hi = 0; hi < 2; hi++) {
                int r = wm * 64 + mi * 16 + hi * 8 + g;
                float zq = zsq_s[r];
                int slot = mi * 2 + hi;
                #pragma unroll
                for (int ni = 0; ni < 4; ni++) {
                    #pragma unroll
                    for (int cc = 0; cc < 2; cc++) {
                        int col = wn * 32 + ni * 8 + 2 * q + cc;
                        float gv = acc[mi][ni][hi * 2 + cc];
                        float sv = __fadd_rn(zq, eqv[ni][cc]) - gv * KSCALE;
                        if (sv < lbest[slot] + MARGIN) {   // rare
                            atomicMin((int*)&minv[r], __float_as_int(sv)); // dist>0
                            float cm = minv[r];
                            if (sv < cm + MARGIN) {
                                int pos = atomicAdd(&cnt_s[r], 1);
                                if (pos < CAP)
                                    cand_s[r * CAP + pos] = (unsigned short)(kt * 128 + col);
                            }
                            if (sv < lbest[slot]) lbest[slot] = sv;
                        }
                    }
                }
            }
        }
    }
    __syncthreads();

    if (t < 128) g_ccnt[n0 + t] = cnt_s[t];
    for (int i = t; i < 128 * CAP; i += 256)
        g_cand[(size_t)n0 * CAP + i] = cand_s[i];
}

// ============================================================
// rescore: EXACT ascending-d FMA chain for candidates only;
// packed-u64 min => lowest-index tie-break. Warp per pixel.
// Overflowed pixels: full exact scan (rare).
// ============================================================
__global__ void __launch_bounds__(256) rescore_kernel(const float* __restrict__ emb) {
    __shared__ float zrow[8][256];
    int t = threadIdx.x, lane = t & 31, w = t >> 5;
    int n = blockIdx.x * 8 + w;

    #pragma unroll
    for (int l = 0; l < 2; l++) {
        int f4 = lane + 32 * l;
        ((float4*)zrow[w])[f4] = ((const float4*)g_z)[(size_t)n * 64 + f4];
    }
    __syncwarp();

    int cnt = g_ccnt[n];
    float zq = g_zsq[n];
    const float4* z4 = (const float4*)zrow[w];
    unsigned long long best = 0xFFFFFFFFFFFFFFFFull;

    int total = (cnt <= CAP) ? cnt : K_CB;
    for (int i = lane; i < total; i += 32) {
        int k = (cnt <= CAP) ? (int)g_cand[(size_t)n * CAP + i] : i;
        float a = 0.f;
        const float4* e4 = (const float4*)(emb + (size_t)k * D_DIM);
        #pragma unroll 8
        for (int d4 = 0; d4 < 64; d4++) {
            float4 ev = e4[d4], zv = z4[d4];
            a = __fmaf_rn(zv.x, ev.x, a);
            a = __fmaf_rn(zv.y, ev.y, a);
            a = __fmaf_rn(zv.z, ev.z, a);
            a = __fmaf_rn(zv.w, ev.w, a);
        }
        float s = __fadd_rn(__fadd_rn(zq, g_esq[k]), -2.f * a);
        unsigned u = __float_as_uint(s);
        u = (u & 0x80000000u) ? ~u : (u | 0x80000000u);
        unsigned long long key = ((unsigned long long)u << 32) | (unsigned)k;
        if (key < best) best = key;
    }
    #pragma unroll
    for (int off = 16; off; off >>= 1) {
        unsigned long long o = __shfl_xor_sync(0xffffffffu, best, off);
        if (o < best) best = o;
    }
    if (lane == 0) g_idx[n] = (int)(best & 0xFFFFFFFFu);
}

// ============================================================
// epilogue: out = fl(z + fl(q - z)); loss partials; histogram
// ============================================================
__global__ __launch_bounds__(256) void epilogue_kernel(const float* __restrict__ emb,
                                                       float* __restrict__ out) {
    __shared__ float st_s[D_DIM * 33];
    __shared__ int idx_s[32];
    __shared__ float wsum[8];
    int t = threadIdx.x;
    int bh = blockIdx.x;
    int b = bh >> 5, h = bh & 31;
    int n0 = bh * 32;

    if (t < 32) idx_s[t] = g_idx[n0 + t];
    __syncthreads();

    float lsum = 0.f;
    for (int p = 0; p < 32; p++) {
        float zv = g_z[(size_t)(n0 + p) * D_DIM + t];
        float qv = emb[(size_t)idx_s[p] * D_DIM + t];
        float diff = __fadd_rn(qv, -zv);
        lsum += diff * diff;
        st_s[t * 33 + p] = __fadd_rn(zv, diff);
    }
    __syncthreads();

    int w = t & 31, dg = t >> 5;
    float* ob = out + (size_t)b * (D_DIM * 1024) + h * 32;
    #pragma unroll 4
    for (int dd = 0; dd < 32; dd++) {
        int d = dg * 32 + dd;
        ob[(size_t)d * 1024 + w] = st_s[d * 33 + w];
    }

    #pragma unroll
    for (int off = 16; off; off >>= 1) lsum += __shfl_xor_sync(0xffffffffu, lsum, off);
    if ((t & 31) == 0) wsum[t >> 5] = lsum;
    __syncthreads();
    if (t == 0) {
        float s = 0.f;
        #pragma unroll
        for (int i = 0; i < 8; i++) s += wsum[i];
        atomicAdd(&g_loss, s);
    }
    if (t < 32) atomicAdd(&g_counts[idx_s[t]], 1u);
}

// ============================================================
// finalize
// ============================================================
__global__ void finalize_kernel(float* __restrict__ out, int out_size) {
    __shared__ float red[512];
    int t = threadIdx.x;
    float s = 0.f;
    for (int k = t; k < K_CB; k += 512) {
        float avg = (float)g_counts[k] / (float)N_PIX;
        s += avg * logf(avg + 1e-10f);
    }
    red[t] = s;
    __syncthreads();
    for (int o = 256; o; o >>= 1) {
        if (t < o) red[t] += red[t + o];
        __syncthreads();
    }
    if (t == 0) {
        out[out_size - 2] = 1.25f * (g_loss / (float)(N_PIX * D_DIM));
        out[out_size - 1] = expf(-red[0]);
    }
}

extern "C" void kernel_launch(void* const* d_in, const int* in_sizes, int n_in,
                              void* d_out, int out_size) {
    const float* x      = (const float*)d_in[0];
    const float* conv_w = (const float*)d_in[1];
    const float* conv_b = (const float*)d_in[2];
    const float* emb    = (const float*)d_in[3];
    float* out = (float*)d_out;

    const int DIST_SMEM = 65536 + 3 * 512 + 16384;   // 83456 B
    cudaFuncSetAttribute(dist_mma_kernel,
                         cudaFuncAttributeMaxDynamicSharedMemorySize, DIST_SMEM);

    prep_kernel<<<257, 256>>>(conv_w);
    esq_kernel<<<16, 256>>>(emb);
    conv_kernel<<<N_PIX / 32, 256>>>(x, conv_b);
    zsq_kernel<<<N_PIX / 256, 256>>>();
    dist_mma_kernel<<<N_PIX / 128, 256, DIST_SMEM>>>();
    rescore_kernel<<<N_PIX / 8, 256>>>(emb);
    epilogue_kernel<<<N_PIX / 32, 256>>>(emb, out);
    finalize_kernel<<<1, 512>>>(out, out_size);
}